// round 10
// baseline (speedup 1.0000x reference)
#include <cuda_runtime.h>
#include <cuda_bf16.h>
#include <cstdint>

#define B_    512
#define C_    20000
#define DE    512
#define KD    2048          // K * Dp = 8 * 256
#define TEMP  0.07f
#define MOM   0.999f
#define NHN   16

// ---------------- scratch (device globals: allocation-free) ----------------
__device__ float g_sim[(size_t)B_ * C_];                 // 41 MB
__device__ float g_invp[C_];                             // 1 / max(||proto||, eps)
__device__ float g_nce[B_];
__device__ float g_align[B_];
__device__ int   g_lab[B_];
__device__ int   g_invmap[C_];                           // class -> batch row (or -1)
__device__ __align__(16) __nv_bfloat16 g_qh[B_ * DE];    // split( q/(|q|*T) ) hi
__device__ __align__(16) __nv_bfloat16 g_ql[B_ * DE];    // lo
__device__ __align__(16) __nv_bfloat16 g_ph[(size_t)C_ * DE]; // split(proto) hi
__device__ __align__(16) __nv_bfloat16 g_pl[(size_t)C_ * DE]; // lo

// ---------------- helpers ----------------
__device__ __forceinline__ uint32_t pack_bf2(float lo, float hi) {
    __nv_bfloat16 a = __float2bfloat16_rn(lo);
    __nv_bfloat16 b = __float2bfloat16_rn(hi);
    return (uint32_t)__bfloat16_as_ushort(a) | ((uint32_t)__bfloat16_as_ushort(b) << 16);
}
__device__ __forceinline__ void cpasync16(uint32_t s, const void* g) {
    asm volatile("cp.async.cg.shared.global [%0], [%1], 16;" :: "r"(s), "l"(g));
}
#define CP_COMMIT() asm volatile("cp.async.commit_group;" ::: "memory")
#define CP_WAIT(n)  asm volatile("cp.async.wait_group %0;" :: "n"(n) : "memory")

// ---------------- 0a: clear inverse label map ----------------
__global__ void clear_invmap() {
    int i = blockIdx.x * blockDim.x + threadIdx.x;
    if (i < C_) g_invmap[i] = -1;
}

// ---------------- 0b: decode labels + scatter inverse map ----------------
__global__ void decode_labels(const int* __restrict__ raw) {
    __shared__ int is64;
    if (threadIdx.x == 0) {
        int odd_or = 0;
        for (int i = 1; i < 64; i += 2) odd_or |= raw[i];
        is64 = (odd_or == 0) ? 1 : 0;
    }
    __syncthreads();
    int t = threadIdx.x;           // 512 threads
    int v = is64 ? raw[2 * t] : raw[t];
    if (v < 0) v = 0;
    if (v >= C_) v = C_ - 1;
    g_lab[t] = v;
    g_invmap[v] = t;               // labels distinct -> no conflicts
}

// ---------------- 2a: EMA update, part bank rows (runs AFTER the GEMM,
// which performs the bulk part-bank copy) ----------------
__global__ void ema_part(const float* __restrict__ pf, const float* __restrict__ pb,
                         float* __restrict__ opb) {
    int b = blockIdx.x;
    int lab = g_lab[b];
    const float om = 1.0f - MOM;
    const float* src_p = pf + (size_t)b * KD;
    const float* old_p = pb + (size_t)lab * KD;
    float*       dst_p = opb + (size_t)lab * KD;
    for (int i = threadIdx.x; i < KD; i += blockDim.x)
        dst_p[i] = MOM * old_p[i] + om * src_p[i];
}

// ---------------- 3: fused embed-bank copy + EMA + inverse norm + bf16 split
// One warp per class row: read ebank (EMA with emb row if labeled), write
// out_eb + invp + hi/lo splits in one pass.
__global__ void proto_fused(const float* __restrict__ ebk, const float* __restrict__ emb,
                            float* __restrict__ oeb) {
    int w = (blockIdx.x * blockDim.x + threadIdx.x) >> 5;
    int lane = threadIdx.x & 31;
    if (w >= C_) return;
    const int inv = g_invmap[w];
    const float4* r = (const float4*)(ebk + (size_t)w * DE);
    float4 v[4];
#pragma unroll
    for (int i = 0; i < 4; i++) v[i] = r[lane + 32 * i];
    if (inv >= 0) {
        const float4* e = (const float4*)(emb + (size_t)inv * DE);
        const float om = 1.0f - MOM;
#pragma unroll
        for (int i = 0; i < 4; i++) {
            float4 ev = e[lane + 32 * i];
            v[i].x = MOM * v[i].x + om * ev.x;
            v[i].y = MOM * v[i].y + om * ev.y;
            v[i].z = MOM * v[i].z + om * ev.z;
            v[i].w = MOM * v[i].w + om * ev.w;
        }
    }
    float s = 0.0f;
#pragma unroll
    for (int i = 0; i < 4; i++)
        s += v[i].x * v[i].x + v[i].y * v[i].y + v[i].z * v[i].z + v[i].w * v[i].w;
#pragma unroll
    for (int o = 16; o; o >>= 1) s += __shfl_xor_sync(0xffffffffu, s, o);
    if (lane == 0) g_invp[w] = 1.0f / fmaxf(sqrtf(s), 1e-12f);

    float4* ob = (float4*)(oeb + (size_t)w * DE);
    uint2* oh = (uint2*)(g_qh + 0);  // placeholder to keep types obvious
    (void)oh;
    uint2* ph = (uint2*)(g_ph + (size_t)w * DE);
    uint2* pl = (uint2*)(g_pl + (size_t)w * DE);
#pragma unroll
    for (int i = 0; i < 4; i++) {
        ob[lane + 32 * i] = v[i];
        float4 x = v[i];
        __nv_bfloat16 hx = __float2bfloat16_rn(x.x), hy = __float2bfloat16_rn(x.y);
        __nv_bfloat16 hz = __float2bfloat16_rn(x.z), hw = __float2bfloat16_rn(x.w);
        uint2 uh, ul;
        uh.x = (uint32_t)__bfloat16_as_ushort(hx) | ((uint32_t)__bfloat16_as_ushort(hy) << 16);
        uh.y = (uint32_t)__bfloat16_as_ushort(hz) | ((uint32_t)__bfloat16_as_ushort(hw) << 16);
        ul.x = pack_bf2(x.x - __bfloat162float(hx), x.y - __bfloat162float(hy));
        ul.y = pack_bf2(x.z - __bfloat162float(hz), x.w - __bfloat162float(hw));
        ph[lane + 32 * i] = uh;
        pl[lane + 32 * i] = ul;
    }
}

// ---------------- 4: query prep — scale by 1/(|q|*T), bf16 hi/lo split ------
__global__ void q_prep(const float* __restrict__ emb) {
    int w = (blockIdx.x * blockDim.x + threadIdx.x) >> 5;
    int lane = threadIdx.x & 31;
    if (w >= B_) return;
    const float4* r = (const float4*)(emb + (size_t)w * DE);
    float4 v[4];
    float s = 0.0f;
#pragma unroll
    for (int i = 0; i < 4; i++) {
        v[i] = r[lane + 32 * i];
        s += v[i].x * v[i].x + v[i].y * v[i].y + v[i].z * v[i].z + v[i].w * v[i].w;
    }
#pragma unroll
    for (int o = 16; o; o >>= 1) s += __shfl_xor_sync(0xffffffffu, s, o);
    float inv = 1.0f / (fmaxf(sqrtf(s), 1e-12f) * TEMP);
    uint2* oh = (uint2*)(g_qh + (size_t)w * DE);
    uint2* ol = (uint2*)(g_ql + (size_t)w * DE);
#pragma unroll
    for (int i = 0; i < 4; i++) {
        float4 x = v[i];
        x.x *= inv; x.y *= inv; x.z *= inv; x.w *= inv;
        __nv_bfloat16 hx = __float2bfloat16_rn(x.x), hy = __float2bfloat16_rn(x.y);
        __nv_bfloat16 hz = __float2bfloat16_rn(x.z), hw = __float2bfloat16_rn(x.w);
        uint2 uh, ul;
        uh.x = (uint32_t)__bfloat16_as_ushort(hx) | ((uint32_t)__bfloat16_as_ushort(hy) << 16);
        uh.y = (uint32_t)__bfloat16_as_ushort(hz) | ((uint32_t)__bfloat16_as_ushort(hw) << 16);
        ul.x = pack_bf2(x.x - __bfloat162float(hx), x.y - __bfloat162float(hy));
        ul.y = pack_bf2(x.z - __bfloat162float(hz), x.w - __bfloat162float(hw));
        oh[lane + 32 * i] = uh;
        ol[lane + 32 * i] = ul;
    }
}

// ---------------- 5: tensor-core sim GEMM + embedded part-bank copy --------
// cp.async double-buffered operands; part-bank copy interleaved with MMA so
// the DRAM copy hides under tensor-pipe work (intra-kernel overlap).
#define SA 40                     // smem row stride in bf16 (80 B)
#define NKT2 (DE / 32)            // 16 k-tiles
#define ARR_B (128 * SA * 2)      // 10240 B per operand array per stage
#define STAGE_B (4 * ARR_B)       // 40960 B per stage
#define GEMM_SMEM (2 * STAGE_B)   // 81920 B
#define CPY_PER_CTA 16384         // float4 per CTA (628 CTAs cover 10.24M)
#define CPY_PER_IT  1024          // float4 per CTA per k-tile (16 iters)

#define LDSM4(r0, r1, r2, r3, addr) \
    asm volatile("ldmatrix.sync.aligned.m8n8.x4.shared.b16 {%0,%1,%2,%3}, [%4];" \
                 : "=r"(r0), "=r"(r1), "=r"(r2), "=r"(r3) : "r"(addr))

#define MMA16816(d, a, b0v, b1v) \
    asm volatile("mma.sync.aligned.m16n8k16.row.col.f32.bf16.bf16.f32 " \
                 "{%0,%1,%2,%3}, {%4,%5,%6,%7}, {%8,%9}, {%0,%1,%2,%3};" \
                 : "+f"(d.x), "+f"(d.y), "+f"(d.z), "+f"(d.w) \
                 : "r"(a[0]), "r"(a[1]), "r"(a[2]), "r"(a[3]), "r"(b0v), "r"(b1v))

__global__ __launch_bounds__(256, 2)
void sim_gemm_tc(const float4* __restrict__ pb4, float4* __restrict__ opb4, int n4) {
    extern __shared__ __align__(16) char smem[];
    const uint32_t sbase = (uint32_t)__cvta_generic_to_shared(smem);

    const int tid  = threadIdx.x;
    const int lane = tid & 31;
    const int wid  = tid >> 5;
    const int wm   = wid & 1;
    const int wn   = wid >> 1;
    const int m_base = wm * 64;
    const int n_base = wn * 32;
    const int row0 = blockIdx.y * 128;
    const int col0 = blockIdx.x * 128;

    // embedded copy slice
    const int cta = blockIdx.y * gridDim.x + blockIdx.x;       // 0..627
    const size_t cpy_base = (size_t)cta * CPY_PER_CTA;

    // fill mapping: thread -> (row lr, k-half of 16 bf16 = 32 B = 2 cp.async)
    const int lr   = tid >> 1;
    const int half = tid & 1;
    const char* gA_h = (const char*)(g_qh + (size_t)(row0 + lr) * DE + half * 16);
    const char* gA_l = (const char*)(g_ql + (size_t)(row0 + lr) * DE + half * 16);
    const char* gB_h = (const char*)(g_ph + (size_t)(col0 + lr) * DE + half * 16);
    const char* gB_l = (const char*)(g_pl + (size_t)(col0 + lr) * DE + half * 16);
    const uint32_t srow = (uint32_t)(lr * SA + half * 16) * 2;

    auto load_stage = [&](int s, int kt) {
        const uint32_t st = sbase + s * STAGE_B + srow;
        const size_t gk = (size_t)kt * 64;
        cpasync16(st + 0 * ARR_B,      gA_h + gk);
        cpasync16(st + 0 * ARR_B + 16, gA_h + gk + 16);
        cpasync16(st + 1 * ARR_B,      gA_l + gk);
        cpasync16(st + 1 * ARR_B + 16, gA_l + gk + 16);
        cpasync16(st + 2 * ARR_B,      gB_h + gk);
        cpasync16(st + 2 * ARR_B + 16, gB_h + gk + 16);
        cpasync16(st + 3 * ARR_B,      gB_l + gk);
        cpasync16(st + 3 * ARR_B + 16, gB_l + gk + 16);
    };

    const int rA = (lane & 7) + ((lane >> 3) & 1) * 8;
    const int cA = ((lane >> 4) & 1) * 8;
    const int rB = (lane & 7) + ((lane >> 4) & 1) * 8;
    const int cB = ((lane >> 3) & 1) * 8;

    float4 acc[4][4];
#pragma unroll
    for (int i = 0; i < 4; i++)
#pragma unroll
        for (int j = 0; j < 4; j++) acc[i][j] = make_float4(0.f, 0.f, 0.f, 0.f);

    load_stage(0, 0);
    CP_COMMIT();

    for (int kt = 0; kt < NKT2; kt++) {
        const int s = kt & 1;
        if (kt + 1 < NKT2) {
            load_stage(s ^ 1, kt + 1);
            CP_COMMIT();
        }

        // ---- embedded part-bank copy: 4 float4 per thread per iteration ----
        {
            float4 cv[4];
            size_t ci[4];
            bool ok[4];
#pragma unroll
            for (int j = 0; j < 4; j++) {
                ci[j] = cpy_base + (size_t)kt * CPY_PER_IT + j * 256 + tid;
                ok[j] = ci[j] < (size_t)n4;
                if (ok[j]) cv[j] = pb4[ci[j]];
            }
#pragma unroll
            for (int j = 0; j < 4; j++)
                if (ok[j]) opb4[ci[j]] = cv[j];
        }

        if (kt + 1 < NKT2) { CP_WAIT(1); } else { CP_WAIT(0); }
        __syncthreads();

        const uint32_t bAh = sbase + s * STAGE_B;
        const uint32_t bAl = bAh + ARR_B;
        const uint32_t bBh = bAh + 2 * ARR_B;
        const uint32_t bBl = bAh + 3 * ARR_B;
#pragma unroll
        for (int kk = 0; kk < 2; kk++) {
            uint32_t Ah[4][4], Al[4][4], Bh[2][4], Bl[2][4];
#pragma unroll
            for (int im = 0; im < 4; im++) {
                uint32_t off = ((m_base + im * 16 + rA) * SA + kk * 16 + cA) * 2;
                LDSM4(Ah[im][0], Ah[im][1], Ah[im][2], Ah[im][3], bAh + off);
                LDSM4(Al[im][0], Al[im][1], Al[im][2], Al[im][3], bAl + off);
            }
#pragma unroll
            for (int t2 = 0; t2 < 2; t2++) {
                uint32_t off = ((n_base + t2 * 16 + rB) * SA + kk * 16 + cB) * 2;
                LDSM4(Bh[t2][0], Bh[t2][1], Bh[t2][2], Bh[t2][3], bBh + off);
                LDSM4(Bl[t2][0], Bl[t2][1], Bl[t2][2], Bl[t2][3], bBl + off);
            }
#pragma unroll
            for (int im = 0; im < 4; im++)
#pragma unroll
                for (int in = 0; in < 4; in++)
                    MMA16816(acc[im][in], Ah[im], Bh[in >> 1][(in & 1) * 2],
                             Bh[in >> 1][(in & 1) * 2 + 1]);
#pragma unroll
            for (int im = 0; im < 4; im++)
#pragma unroll
                for (int in = 0; in < 4; in++)
                    MMA16816(acc[im][in], Ah[im], Bl[in >> 1][(in & 1) * 2],
                             Bl[in >> 1][(in & 1) * 2 + 1]);
#pragma unroll
            for (int im = 0; im < 4; im++)
#pragma unroll
                for (int in = 0; in < 4; in++)
                    MMA16816(acc[im][in], Al[im], Bh[in >> 1][(in & 1) * 2],
                             Bh[in >> 1][(in & 1) * 2 + 1]);
        }
        __syncthreads();
    }

    // epilogue: scale by invp[col], write g_sim
    const int gq = lane >> 2;
    const int qp = (lane & 3) * 2;
#pragma unroll
    for (int im = 0; im < 4; im++) {
        const int r = row0 + m_base + im * 16 + gq;
        float* row_ptr0 = g_sim + (size_t)r * C_;
        float* row_ptr1 = g_sim + (size_t)(r + 8) * C_;
#pragma unroll
        for (int in = 0; in < 4; in++) {
            const int c = col0 + n_base + in * 8 + qp;
            if (c < C_) {
                const float ip0 = g_invp[c];
                const float ip1 = g_invp[c + 1];
                float4 a = acc[im][in];
                float2 lo = make_float2(a.x * ip0, a.y * ip1);
                float2 hi = make_float2(a.z * ip0, a.w * ip1);
                *(float2*)(row_ptr0 + c) = lo;
                *(float2*)(row_ptr1 + c) = hi;
            }
        }
    }
}

// ---------------- 6: top-16 negatives + logsumexp per row ----------------
__global__ __launch_bounds__(256)
void topk_lse() {
    __shared__ float cand[256 * NHN];
    const int b = blockIdx.x;
    const int tid = threadIdx.x;
    const int lab = g_lab[b];
    const float* row = g_sim + (size_t)b * C_;

    float lt[NHN];
#pragma unroll
    for (int i = 0; i < NHN; i++) lt[i] = -1e30f;

    const float4* row4 = (const float4*)row;
    for (int c4 = tid; c4 < C_ / 4; c4 += 256) {
        float4 v4 = row4[c4];
        const int cb = c4 * 4;
        float vv[4] = {v4.x, v4.y, v4.z, v4.w};
#pragma unroll
        for (int j = 0; j < 4; j++) {
            if (cb + j == lab) continue;
            float v = vv[j];
            if (v > lt[NHN - 1]) {
                int k = NHN - 1;
                while (k > 0 && lt[k - 1] < v) { lt[k] = lt[k - 1]; --k; }
                lt[k] = v;
            }
        }
    }
#pragma unroll
    for (int i = 0; i < NHN; i++) cand[tid * NHN + i] = lt[i];

    for (int s = 128; s >= 1; s >>= 1) {
        __syncthreads();
        if (tid < s) {
            const float* Aa = cand + tid * NHN;
            const float* Bb = cand + (tid + s) * NHN;
            float out[NHN];
            int i = 0, j = 0;
#pragma unroll
            for (int t = 0; t < NHN; t++) {
                float a = Aa[i], bv = Bb[j];
                if (a >= bv) { out[t] = a; i++; } else { out[t] = bv; j++; }
            }
#pragma unroll
            for (int t = 0; t < NHN; t++) cand[tid * NHN + t] = out[t];
        }
    }
    __syncthreads();
    if (tid == 0) {
        float pos = row[lab];
        float mx = pos;
#pragma unroll
        for (int i = 0; i < NHN; i++) mx = fmaxf(mx, cand[i]);
        float sum = __expf(pos - mx);
#pragma unroll
        for (int i = 0; i < NHN; i++) sum += __expf(cand[i] - mx);
        g_nce[b] = mx + logf(sum) - pos;
    }
}

// ---------------- 7: alignment loss per row ----------------
__global__ __launch_bounds__(256)
void align_row(const float* __restrict__ emb, const float* __restrict__ sat,
               const float* __restrict__ neb) {
    __shared__ float red[5][8];
    const int b = blockIdx.x;
    const int tid = threadIdx.x;
    const int lab = g_lab[b];
    const float* e = emb + (size_t)b * DE;
    const float* s = sat + (size_t)b * DE;
    const float* p = neb + (size_t)lab * DE;
    float ee = 0, ss = 0, pp = 0, ep = 0, sp = 0;
    for (int i = tid; i < DE; i += 256) {
        float ev = e[i], sv = s[i], pv = p[i];
        ee += ev * ev; ss += sv * sv; pp += pv * pv;
        ep += ev * pv; sp += sv * pv;
    }
#pragma unroll
    for (int o = 16; o; o >>= 1) {
        ee += __shfl_xor_sync(0xffffffffu, ee, o);
        ss += __shfl_xor_sync(0xffffffffu, ss, o);
        pp += __shfl_xor_sync(0xffffffffu, pp, o);
        ep += __shfl_xor_sync(0xffffffffu, ep, o);
        sp += __shfl_xor_sync(0xffffffffu, sp, o);
    }
    int w = tid >> 5;
    if ((tid & 31) == 0) {
        red[0][w] = ee; red[1][w] = ss; red[2][w] = pp; red[3][w] = ep; red[4][w] = sp;
    }
    __syncthreads();
    if (tid == 0) {
        float a0 = 0, a1 = 0, a2 = 0, a3 = 0, a4 = 0;
        for (int i = 0; i < 8; i++) {
            a0 += red[0][i]; a1 += red[1][i]; a2 += red[2][i];
            a3 += red[3][i]; a4 += red[4][i];
        }
        float dn = fmaxf(sqrtf(a0), 1e-12f);
        float sn = fmaxf(sqrtf(a1), 1e-12f);
        float pn = fmaxf(sqrtf(a2), 1e-12f);
        g_align[b] = 0.5f * ((1.0f - a3 / (dn * pn)) + (1.0f - a4 / (sn * pn)));
    }
}

// ---------------- 8: final scalar reduction ----------------
__global__ __launch_bounds__(512)
void finalize(float* __restrict__ out_loss) {
    __shared__ float s1[512], s2[512];
    int t = threadIdx.x;
    s1[t] = g_nce[t];
    s2[t] = g_align[t];
    __syncthreads();
    for (int s = 256; s >= 1; s >>= 1) {
        if (t < s) { s1[t] += s1[t + s]; s2[t] += s2[t + s]; }
        __syncthreads();
    }
    if (t == 0) {
        out_loss[0] = s1[0] / (float)B_;
        out_loss[1] = s2[0] / (float)B_;
    }
}

// ---------------- launch ----------------
extern "C" void kernel_launch(void* const* d_in, const int* in_sizes, int n_in,
                              void* d_out, int out_size) {
    const float* pf    = (const float*)d_in[0];     // [512, 8, 256]
    const float* emb   = (const float*)d_in[1];     // [512, 512]
    const float* sat   = (const float*)d_in[2];     // [512, 512]
    const float* pbank = (const float*)d_in[3];     // [20000, 8, 256]
    const float* ebank = (const float*)d_in[4];     // [20000, 512]
    const int*   labs  = (const int*)d_in[5];       // [512] int32/int64 auto-detected

    const int P = in_sizes[3];   // 40,960,000
    const int E = in_sizes[4];   // 10,240,000

    float* out    = (float*)d_out;
    float* out_pb = out;
    float* out_eb = out + P;
    float* out_ls = out + P + E;

    static bool attr_done = false;
    if (!attr_done) {
        cudaFuncSetAttribute(sim_gemm_tc,
                             cudaFuncAttributeMaxDynamicSharedMemorySize, GEMM_SMEM);
        attr_done = true;
    }

    // 0. labels + inverse map
    clear_invmap<<<(C_ + 255) / 256, 256>>>();
    decode_labels<<<1, B_>>>(labs);
    // 1. fused embed copy + EMA + norms + bf16 split (one pass over ebank)
    proto_fused<<<(C_ + 7) / 8, 256>>>(ebank, emb, out_eb);
    // 2. scaled queries + split
    q_prep<<<(B_ + 7) / 8, 256>>>(emb);
    // 3. GEMM with embedded part-bank copy (intra-kernel DRAM/tensor overlap)
    dim3 ggrid((C_ + 127) / 128, B_ / 128);
    sim_gemm_tc<<<ggrid, 256, GEMM_SMEM>>>((const float4*)pbank, (float4*)out_pb, P / 4);
    // 4. EMA on part rows (after the GEMM-embedded copy)
    ema_part<<<B_, 256>>>(pf, pbank, out_pb);
    // 5. top-k + logsumexp
    topk_lse<<<B_, 256>>>();
    // 6. alignment
    align_row<<<B_, 256>>>(emb, sat, out_eb);
    // 7. finalize scalars
    finalize<<<1, 512>>>(out_ls);
}

// round 11
// speedup vs baseline: 1.0454x; 1.0454x over previous
#include <cuda_runtime.h>
#include <cuda_bf16.h>
#include <cstdint>

#define B_    512
#define C_    20000
#define DE    512
#define KD    2048          // K * Dp = 8 * 256
#define TEMP  0.07f
#define MOM   0.999f
#define NHN   16

// ---------------- scratch (device globals: allocation-free) ----------------
__device__ float g_sim[(size_t)B_ * C_];                 // 41 MB
__device__ float g_invp[C_];                             // 1 / max(||proto||, eps)
__device__ float g_nce[B_];
__device__ float g_align[B_];
__device__ int   g_lab[B_];
__device__ int   g_invmap[C_];                           // class -> batch row (or -1)
__device__ __align__(16) __nv_bfloat16 g_qh[B_ * DE];    // split( q/(|q|*T) ) hi
__device__ __align__(16) __nv_bfloat16 g_ql[B_ * DE];    // lo
__device__ __align__(16) __nv_bfloat16 g_ph[(size_t)C_ * DE]; // split(proto) hi
__device__ __align__(16) __nv_bfloat16 g_pl[(size_t)C_ * DE]; // lo

// ---------------- helpers ----------------
__device__ __forceinline__ uint32_t pack_bf2(float lo, float hi) {
    __nv_bfloat16 a = __float2bfloat16_rn(lo);
    __nv_bfloat16 b = __float2bfloat16_rn(hi);
    return (uint32_t)__bfloat16_as_ushort(a) | ((uint32_t)__bfloat16_as_ushort(b) << 16);
}
__device__ __forceinline__ void cpasync16(uint32_t s, const void* g) {
    asm volatile("cp.async.cg.shared.global [%0], [%1], 16;" :: "r"(s), "l"(g));
}
#define CP_COMMIT() asm volatile("cp.async.commit_group;" ::: "memory")
#define CP_WAIT(n)  asm volatile("cp.async.wait_group %0;" :: "n"(n) : "memory")

// ---------------- 0a: clear inverse label map ----------------
__global__ void clear_invmap() {
    int i = blockIdx.x * blockDim.x + threadIdx.x;
    if (i < C_) g_invmap[i] = -1;
}

// ---------------- 0b: decode labels + scatter inverse map ----------------
__global__ void decode_labels(const int* __restrict__ raw) {
    __shared__ int is64;
    if (threadIdx.x == 0) {
        int odd_or = 0;
        for (int i = 1; i < 64; i += 2) odd_or |= raw[i];
        is64 = (odd_or == 0) ? 1 : 0;
    }
    __syncthreads();
    int t = threadIdx.x;           // 512 threads
    int v = is64 ? raw[2 * t] : raw[t];
    if (v < 0) v = 0;
    if (v >= C_) v = C_ - 1;
    g_lab[t] = v;
    g_invmap[v] = t;               // labels distinct -> no conflicts
}

// ---------------- 1: part-bank copy (standalone, full-bandwidth grid) -------
__global__ void copy_buf(const float4* __restrict__ src, float4* __restrict__ dst, int n4) {
    for (int i = blockIdx.x * blockDim.x + threadIdx.x; i < n4;
         i += gridDim.x * blockDim.x)
        dst[i] = src[i];
}

// ---------------- 2: EMA update, part bank rows ----------------
__global__ void ema_part(const float* __restrict__ pf, const float* __restrict__ pb,
                         float* __restrict__ opb) {
    int b = blockIdx.x;
    int lab = g_lab[b];
    const float om = 1.0f - MOM;
    const float* src_p = pf + (size_t)b * KD;
    const float* old_p = pb + (size_t)lab * KD;
    float*       dst_p = opb + (size_t)lab * KD;
    for (int i = threadIdx.x; i < KD; i += blockDim.x)
        dst_p[i] = MOM * old_p[i] + om * src_p[i];
}

// ---------------- 3: fused embed-bank copy + EMA + inverse norm + bf16 split
__global__ void proto_fused(const float* __restrict__ ebk, const float* __restrict__ emb,
                            float* __restrict__ oeb) {
    int w = (blockIdx.x * blockDim.x + threadIdx.x) >> 5;
    int lane = threadIdx.x & 31;
    if (w >= C_) return;
    const int inv = g_invmap[w];
    const float4* r = (const float4*)(ebk + (size_t)w * DE);
    float4 v[4];
#pragma unroll
    for (int i = 0; i < 4; i++) v[i] = r[lane + 32 * i];
    if (inv >= 0) {
        const float4* e = (const float4*)(emb + (size_t)inv * DE);
        const float om = 1.0f - MOM;
#pragma unroll
        for (int i = 0; i < 4; i++) {
            float4 ev = e[lane + 32 * i];
            v[i].x = MOM * v[i].x + om * ev.x;
            v[i].y = MOM * v[i].y + om * ev.y;
            v[i].z = MOM * v[i].z + om * ev.z;
            v[i].w = MOM * v[i].w + om * ev.w;
        }
    }
    float s = 0.0f;
#pragma unroll
    for (int i = 0; i < 4; i++)
        s += v[i].x * v[i].x + v[i].y * v[i].y + v[i].z * v[i].z + v[i].w * v[i].w;
#pragma unroll
    for (int o = 16; o; o >>= 1) s += __shfl_xor_sync(0xffffffffu, s, o);
    if (lane == 0) g_invp[w] = 1.0f / fmaxf(sqrtf(s), 1e-12f);

    float4* ob = (float4*)(oeb + (size_t)w * DE);
    uint2* ph = (uint2*)(g_ph + (size_t)w * DE);
    uint2* pl = (uint2*)(g_pl + (size_t)w * DE);
#pragma unroll
    for (int i = 0; i < 4; i++) {
        ob[lane + 32 * i] = v[i];
        float4 x = v[i];
        __nv_bfloat16 hx = __float2bfloat16_rn(x.x), hy = __float2bfloat16_rn(x.y);
        __nv_bfloat16 hz = __float2bfloat16_rn(x.z), hw = __float2bfloat16_rn(x.w);
        uint2 uh, ul;
        uh.x = (uint32_t)__bfloat16_as_ushort(hx) | ((uint32_t)__bfloat16_as_ushort(hy) << 16);
        uh.y = (uint32_t)__bfloat16_as_ushort(hz) | ((uint32_t)__bfloat16_as_ushort(hw) << 16);
        ul.x = pack_bf2(x.x - __bfloat162float(hx), x.y - __bfloat162float(hy));
        ul.y = pack_bf2(x.z - __bfloat162float(hz), x.w - __bfloat162float(hw));
        ph[lane + 32 * i] = uh;
        pl[lane + 32 * i] = ul;
    }
}

// ---------------- 4: query prep — scale by 1/(|q|*T), bf16 hi/lo split ------
__global__ void q_prep(const float* __restrict__ emb) {
    int w = (blockIdx.x * blockDim.x + threadIdx.x) >> 5;
    int lane = threadIdx.x & 31;
    if (w >= B_) return;
    const float4* r = (const float4*)(emb + (size_t)w * DE);
    float4 v[4];
    float s = 0.0f;
#pragma unroll
    for (int i = 0; i < 4; i++) {
        v[i] = r[lane + 32 * i];
        s += v[i].x * v[i].x + v[i].y * v[i].y + v[i].z * v[i].z + v[i].w * v[i].w;
    }
#pragma unroll
    for (int o = 16; o; o >>= 1) s += __shfl_xor_sync(0xffffffffu, s, o);
    float inv = 1.0f / (fmaxf(sqrtf(s), 1e-12f) * TEMP);
    uint2* oh = (uint2*)(g_qh + (size_t)w * DE);
    uint2* ol = (uint2*)(g_ql + (size_t)w * DE);
#pragma unroll
    for (int i = 0; i < 4; i++) {
        float4 x = v[i];
        x.x *= inv; x.y *= inv; x.z *= inv; x.w *= inv;
        __nv_bfloat16 hx = __float2bfloat16_rn(x.x), hy = __float2bfloat16_rn(x.y);
        __nv_bfloat16 hz = __float2bfloat16_rn(x.z), hw = __float2bfloat16_rn(x.w);
        uint2 uh, ul;
        uh.x = (uint32_t)__bfloat16_as_ushort(hx) | ((uint32_t)__bfloat16_as_ushort(hy) << 16);
        uh.y = (uint32_t)__bfloat16_as_ushort(hz) | ((uint32_t)__bfloat16_as_ushort(hw) << 16);
        ul.x = pack_bf2(x.x - __bfloat162float(hx), x.y - __bfloat162float(hy));
        ul.y = pack_bf2(x.z - __bfloat162float(hz), x.w - __bfloat162float(hw));
        oh[lane + 32 * i] = uh;
        ol[lane + 32 * i] = ul;
    }
}

// ---------------- 5: tensor-core sim GEMM (R9-proven body) ------------------
#define SA 40                     // smem row stride in bf16 (80 B)
#define NKT2 (DE / 32)            // 16 k-tiles
#define ARR_B (128 * SA * 2)      // 10240 B per operand array per stage
#define STAGE_B (4 * ARR_B)       // 40960 B per stage
#define GEMM_SMEM (2 * STAGE_B)   // 81920 B

#define LDSM4(r0, r1, r2, r3, addr) \
    asm volatile("ldmatrix.sync.aligned.m8n8.x4.shared.b16 {%0,%1,%2,%3}, [%4];" \
                 : "=r"(r0), "=r"(r1), "=r"(r2), "=r"(r3) : "r"(addr))

#define MMA16816(d, a, b0v, b1v) \
    asm volatile("mma.sync.aligned.m16n8k16.row.col.f32.bf16.bf16.f32 " \
                 "{%0,%1,%2,%3}, {%4,%5,%6,%7}, {%8,%9}, {%0,%1,%2,%3};" \
                 : "+f"(d.x), "+f"(d.y), "+f"(d.z), "+f"(d.w) \
                 : "r"(a[0]), "r"(a[1]), "r"(a[2]), "r"(a[3]), "r"(b0v), "r"(b1v))

__global__ __launch_bounds__(256, 2)
void sim_gemm_tc() {
    extern __shared__ __align__(16) char smem[];
    const uint32_t sbase = (uint32_t)__cvta_generic_to_shared(smem);

    const int tid  = threadIdx.x;
    const int lane = tid & 31;
    const int wid  = tid >> 5;
    const int wm   = wid & 1;
    const int wn   = wid >> 1;
    const int m_base = wm * 64;
    const int n_base = wn * 32;
    const int row0 = blockIdx.y * 128;
    const int col0 = blockIdx.x * 128;

    const int lr   = tid >> 1;
    const int half = tid & 1;
    const char* gA_h = (const char*)(g_qh + (size_t)(row0 + lr) * DE + half * 16);
    const char* gA_l = (const char*)(g_ql + (size_t)(row0 + lr) * DE + half * 16);
    const char* gB_h = (const char*)(g_ph + (size_t)(col0 + lr) * DE + half * 16);
    const char* gB_l = (const char*)(g_pl + (size_t)(col0 + lr) * DE + half * 16);
    const uint32_t srow = (uint32_t)(lr * SA + half * 16) * 2;

    auto load_stage = [&](int s, int kt) {
        const uint32_t st = sbase + s * STAGE_B + srow;
        const size_t gk = (size_t)kt * 64;
        cpasync16(st + 0 * ARR_B,      gA_h + gk);
        cpasync16(st + 0 * ARR_B + 16, gA_h + gk + 16);
        cpasync16(st + 1 * ARR_B,      gA_l + gk);
        cpasync16(st + 1 * ARR_B + 16, gA_l + gk + 16);
        cpasync16(st + 2 * ARR_B,      gB_h + gk);
        cpasync16(st + 2 * ARR_B + 16, gB_h + gk + 16);
        cpasync16(st + 3 * ARR_B,      gB_l + gk);
        cpasync16(st + 3 * ARR_B + 16, gB_l + gk + 16);
    };

    const int rA = (lane & 7) + ((lane >> 3) & 1) * 8;
    const int cA = ((lane >> 4) & 1) * 8;
    const int rB = (lane & 7) + ((lane >> 4) & 1) * 8;
    const int cB = ((lane >> 3) & 1) * 8;

    float4 acc[4][4];
#pragma unroll
    for (int i = 0; i < 4; i++)
#pragma unroll
        for (int j = 0; j < 4; j++) acc[i][j] = make_float4(0.f, 0.f, 0.f, 0.f);

    load_stage(0, 0);
    CP_COMMIT();

    for (int kt = 0; kt < NKT2; kt++) {
        const int s = kt & 1;
        if (kt + 1 < NKT2) {
            load_stage(s ^ 1, kt + 1);
            CP_COMMIT();
            CP_WAIT(1);
        } else {
            CP_WAIT(0);
        }
        __syncthreads();

        const uint32_t bAh = sbase + s * STAGE_B;
        const uint32_t bAl = bAh + ARR_B;
        const uint32_t bBh = bAh + 2 * ARR_B;
        const uint32_t bBl = bAh + 3 * ARR_B;
#pragma unroll
        for (int kk = 0; kk < 2; kk++) {
            uint32_t Ah[4][4], Al[4][4], Bh[2][4], Bl[2][4];
#pragma unroll
            for (int im = 0; im < 4; im++) {
                uint32_t off = ((m_base + im * 16 + rA) * SA + kk * 16 + cA) * 2;
                LDSM4(Ah[im][0], Ah[im][1], Ah[im][2], Ah[im][3], bAh + off);
                LDSM4(Al[im][0], Al[im][1], Al[im][2], Al[im][3], bAl + off);
            }
#pragma unroll
            for (int t2 = 0; t2 < 2; t2++) {
                uint32_t off = ((n_base + t2 * 16 + rB) * SA + kk * 16 + cB) * 2;
                LDSM4(Bh[t2][0], Bh[t2][1], Bh[t2][2], Bh[t2][3], bBh + off);
                LDSM4(Bl[t2][0], Bl[t2][1], Bl[t2][2], Bl[t2][3], bBl + off);
            }
#pragma unroll
            for (int im = 0; im < 4; im++)
#pragma unroll
                for (int in = 0; in < 4; in++)
                    MMA16816(acc[im][in], Ah[im], Bh[in >> 1][(in & 1) * 2],
                             Bh[in >> 1][(in & 1) * 2 + 1]);
#pragma unroll
            for (int im = 0; im < 4; im++)
#pragma unroll
                for (int in = 0; in < 4; in++)
                    MMA16816(acc[im][in], Ah[im], Bl[in >> 1][(in & 1) * 2],
                             Bl[in >> 1][(in & 1) * 2 + 1]);
#pragma unroll
            for (int im = 0; im < 4; im++)
#pragma unroll
                for (int in = 0; in < 4; in++)
                    MMA16816(acc[im][in], Al[im], Bh[in >> 1][(in & 1) * 2],
                             Bh[in >> 1][(in & 1) * 2 + 1]);
        }
        __syncthreads();
    }

    // epilogue: scale by invp[col], write g_sim
    const int gq = lane >> 2;
    const int qp = (lane & 3) * 2;
#pragma unroll
    for (int im = 0; im < 4; im++) {
        const int r = row0 + m_base + im * 16 + gq;
        float* row_ptr0 = g_sim + (size_t)r * C_;
        float* row_ptr1 = g_sim + (size_t)(r + 8) * C_;
#pragma unroll
        for (int in = 0; in < 4; in++) {
            const int c = col0 + n_base + in * 8 + qp;
            if (c < C_) {
                const float ip0 = g_invp[c];
                const float ip1 = g_invp[c + 1];
                float4 a = acc[im][in];
                float2 lo = make_float2(a.x * ip0, a.y * ip1);
                float2 hi = make_float2(a.z * ip0, a.w * ip1);
                *(float2*)(row_ptr0 + c) = lo;
                *(float2*)(row_ptr1 + c) = hi;
            }
        }
    }
}

// ---------------- 6: top-16 negatives + logsumexp per row ----------------
__global__ __launch_bounds__(256)
void topk_lse() {
    __shared__ float cand[256 * NHN];
    const int b = blockIdx.x;
    const int tid = threadIdx.x;
    const int lab = g_lab[b];
    const float* row = g_sim + (size_t)b * C_;

    float lt[NHN];
#pragma unroll
    for (int i = 0; i < NHN; i++) lt[i] = -1e30f;

    const float4* row4 = (const float4*)row;
    for (int c4 = tid; c4 < C_ / 4; c4 += 256) {
        float4 v4 = row4[c4];
        const int cb = c4 * 4;
        float vv[4] = {v4.x, v4.y, v4.z, v4.w};
#pragma unroll
        for (int j = 0; j < 4; j++) {
            if (cb + j == lab) continue;
            float v = vv[j];
            if (v > lt[NHN - 1]) {
                int k = NHN - 1;
                while (k > 0 && lt[k - 1] < v) { lt[k] = lt[k - 1]; --k; }
                lt[k] = v;
            }
        }
    }
#pragma unroll
    for (int i = 0; i < NHN; i++) cand[tid * NHN + i] = lt[i];

    for (int s = 128; s >= 1; s >>= 1) {
        __syncthreads();
        if (tid < s) {
            const float* Aa = cand + tid * NHN;
            const float* Bb = cand + (tid + s) * NHN;
            float out[NHN];
            int i = 0, j = 0;
#pragma unroll
            for (int t = 0; t < NHN; t++) {
                float a = Aa[i], bv = Bb[j];
                if (a >= bv) { out[t] = a; i++; } else { out[t] = bv; j++; }
            }
#pragma unroll
            for (int t = 0; t < NHN; t++) cand[tid * NHN + t] = out[t];
        }
    }
    __syncthreads();
    if (tid == 0) {
        float pos = row[lab];
        float mx = pos;
#pragma unroll
        for (int i = 0; i < NHN; i++) mx = fmaxf(mx, cand[i]);
        float sum = __expf(pos - mx);
#pragma unroll
        for (int i = 0; i < NHN; i++) sum += __expf(cand[i] - mx);
        g_nce[b] = mx + logf(sum) - pos;
    }
}

// ---------------- 7: alignment loss per row ----------------
__global__ __launch_bounds__(256)
void align_row(const float* __restrict__ emb, const float* __restrict__ sat,
               const float* __restrict__ neb) {
    __shared__ float red[5][8];
    const int b = blockIdx.x;
    const int tid = threadIdx.x;
    const int lab = g_lab[b];
    const float* e = emb + (size_t)b * DE;
    const float* s = sat + (size_t)b * DE;
    const float* p = neb + (size_t)lab * DE;
    float ee = 0, ss = 0, pp = 0, ep = 0, sp = 0;
    for (int i = tid; i < DE; i += 256) {
        float ev = e[i], sv = s[i], pv = p[i];
        ee += ev * ev; ss += sv * sv; pp += pv * pv;
        ep += ev * pv; sp += sv * pv;
    }
#pragma unroll
    for (int o = 16; o; o >>= 1) {
        ee += __shfl_xor_sync(0xffffffffu, ee, o);
        ss += __shfl_xor_sync(0xffffffffu, ss, o);
        pp += __shfl_xor_sync(0xffffffffu, pp, o);
        ep += __shfl_xor_sync(0xffffffffu, ep, o);
        sp += __shfl_xor_sync(0xffffffffu, sp, o);
    }
    int w = tid >> 5;
    if ((tid & 31) == 0) {
        red[0][w] = ee; red[1][w] = ss; red[2][w] = pp; red[3][w] = ep; red[4][w] = sp;
    }
    __syncthreads();
    if (tid == 0) {
        float a0 = 0, a1 = 0, a2 = 0, a3 = 0, a4 = 0;
        for (int i = 0; i < 8; i++) {
            a0 += red[0][i]; a1 += red[1][i]; a2 += red[2][i];
            a3 += red[3][i]; a4 += red[4][i];
        }
        float dn = fmaxf(sqrtf(a0), 1e-12f);
        float sn = fmaxf(sqrtf(a1), 1e-12f);
        float pn = fmaxf(sqrtf(a2), 1e-12f);
        g_align[b] = 0.5f * ((1.0f - a3 / (dn * pn)) + (1.0f - a4 / (sn * pn)));
    }
}

// ---------------- 8: final scalar reduction ----------------
__global__ __launch_bounds__(512)
void finalize(float* __restrict__ out_loss) {
    __shared__ float s1[512], s2[512];
    int t = threadIdx.x;
    s1[t] = g_nce[t];
    s2[t] = g_align[t];
    __syncthreads();
    for (int s = 256; s >= 1; s >>= 1) {
        if (t < s) { s1[t] += s1[t + s]; s2[t] += s2[t + s]; }
        __syncthreads();
    }
    if (t == 0) {
        out_loss[0] = s1[0] / (float)B_;
        out_loss[1] = s2[0] / (float)B_;
    }
}

// ---------------- launch ----------------
extern "C" void kernel_launch(void* const* d_in, const int* in_sizes, int n_in,
                              void* d_out, int out_size) {
    const float* pf    = (const float*)d_in[0];     // [512, 8, 256]
    const float* emb   = (const float*)d_in[1];     // [512, 512]
    const float* sat   = (const float*)d_in[2];     // [512, 512]
    const float* pbank = (const float*)d_in[3];     // [20000, 8, 256]
    const float* ebank = (const float*)d_in[4];     // [20000, 512]
    const int*   labs  = (const int*)d_in[5];       // [512] int32/int64 auto-detected

    const int P = in_sizes[3];   // 40,960,000
    const int E = in_sizes[4];   // 10,240,000

    float* out    = (float*)d_out;
    float* out_pb = out;
    float* out_eb = out + P;
    float* out_ls = out + P + E;

    static bool attr_done = false;
    if (!attr_done) {
        cudaFuncSetAttribute(sim_gemm_tc,
                             cudaFuncAttributeMaxDynamicSharedMemorySize, GEMM_SMEM);
        attr_done = true;
    }

    // 0. labels + inverse map
    clear_invmap<<<(C_ + 255) / 256, 256>>>();
    decode_labels<<<1, B_>>>(labs);
    // 1. part-bank copy (standalone, proven full bandwidth)
    copy_buf<<<2048, 256>>>((const float4*)pbank, (float4*)out_pb, P / 4);
    // 2. EMA on part rows
    ema_part<<<B_, 256>>>(pf, pbank, out_pb);
    // 3. fused embed copy + EMA + norms + bf16 split (one pass over ebank)
    proto_fused<<<(C_ + 7) / 8, 256>>>(ebank, emb, out_eb);
    // 4. scaled queries + split
    q_prep<<<(B_ + 7) / 8, 256>>>(emb);
    // 5. GEMM (R9-proven body)
    dim3 ggrid((C_ + 127) / 128, B_ / 128);
    sim_gemm_tc<<<ggrid, 256, GEMM_SMEM>>>();
    // 6. top-k + logsumexp
    topk_lse<<<B_, 256>>>();
    // 7. alignment
    align_row<<<B_, 256>>>(emb, sat, out_eb);
    // 8. finalize scalars
    finalize<<<1, 512>>>(out_ls);
}